// round 11
// baseline (speedup 1.0000x reference)
#include <cuda_runtime.h>
#include <math.h>

// Problem constants
#define B_ 256
#define T_ 128
#define D_ 256
#define U_ 512
#define G5 2560   // 5*U
#define G4 2048   // 4*U
#define G3 1536   // 3*U

#define NBLK 128
#define NTHR 256          // 8 warps, 2 K-split sets
#define KT2 64            // staged K chunk
#define ASTR 68           // A smem row stride ([m][k], floats)
#define BSL 32            // B smem stride per (kk,gate): exactly 128B

// Scratch (device globals: allocation-free per harness rules)
__device__ float g_xg[(long)B_ * T_ * G5];
__device__ float g_h [B_ * U_];
__device__ float g_h1a[B_ * U_];
__device__ float g_h1b[B_ * U_];
__device__ unsigned g_bar_grp[8 * 32];   // per-m-group counters, 128B apart

__device__ __forceinline__ float hsig(float x) {
    return fminf(fmaxf(0.2f * x + 0.5f, 0.0f), 1.0f);
}

typedef unsigned long long ull;
__device__ __forceinline__ ull pk(float x) {
    ull r; asm("mov.b64 %0, {%1, %1};" : "=l"(r) : "f"(x)); return r;
}
__device__ __forceinline__ ull f2(ull a, ull b, ull c) {
    ull d; asm("fma.rn.f32x2 %0, %1, %2, %3;" : "=l"(d) : "l"(a), "l"(b), "l"(c));
    return d;
}
__device__ __forceinline__ ull a2(ull a, ull b) {
    ull d; asm("add.rn.f32x2 %0, %1, %2;" : "=l"(d) : "l"(a), "l"(b));
    return d;
}
__device__ __forceinline__ float2 up(ull v) {
    float2 r; asm("mov.b64 {%0, %1}, %2;" : "=f"(r.x), "=f"(r.y) : "l"(v));
    return r;
}

// ---------------------------------------------------------------------------
__global__ void init_h_kernel(const float* __restrict__ h0) {
    int i = blockIdx.x * blockDim.x + threadIdx.x;
    if (i < B_ * U_) g_h[i] = h0[i];
    if (i < 8 * 32) g_bar_grp[i] = 0;
}

// ---------------------------------------------------------------------------
// xg = x @ kernel + bias[0].  (known-good R8 version)
// ---------------------------------------------------------------------------
#define XASL 132
__global__ void __launch_bounds__(256)
xg_gemm_kernel(const float* __restrict__ X,
               const float* __restrict__ W,
               const float* __restrict__ bias) {
    __shared__ float As[8 * XASL];
    __shared__ float Bs[8 * 128];
    const int bm = blockIdx.y * 128;
    const int bn = blockIdx.x * 128;
    const int tid  = threadIdx.x;
    const int lane = tid & 31;
    const int wrp  = tid >> 5;
    const int mG = lane & 3, nG = lane >> 2;
    const int mW = wrp & 3,  nW = wrp >> 2;
    const int mOff = mW * 32 + mG * 8;
    const int nOff = nW * 64 + nG * 8;
    const int arow = tid >> 1, acol = (tid & 1) * 4;
    const int brow = tid >> 5, bcol = (tid & 31) * 4;

    ull acc[8][4];
#pragma unroll
    for (int i = 0; i < 8; i++)
#pragma unroll
        for (int j = 0; j < 4; j++) acc[i][j] = 0ull;

    const float* Xp = X + (bm + arow) * D_ + acol;
    const float* Wp = W + brow * G5 + bn + bcol;

    for (int k0 = 0; k0 < D_; k0 += 8) {
        float4 av = *(const float4*)(Xp + k0);
        As[(acol + 0) * XASL + arow] = av.x;
        As[(acol + 1) * XASL + arow] = av.y;
        As[(acol + 2) * XASL + arow] = av.z;
        As[(acol + 3) * XASL + arow] = av.w;
        *(float4*)&Bs[brow * 128 + bcol] = *(const float4*)(Wp + (long)k0 * G5);
        __syncthreads();
#pragma unroll
        for (int k = 0; k < 8; k++) {
            float4 a0 = *(const float4*)(As + k * XASL + mOff);
            float4 a1 = *(const float4*)(As + k * XASL + mOff + 4);
            ull a[8] = {pk(a0.x), pk(a0.y), pk(a0.z), pk(a0.w),
                        pk(a1.x), pk(a1.y), pk(a1.z), pk(a1.w)};
            const ulonglong2* bp = (const ulonglong2*)(Bs + k * 128 + nOff);
            ulonglong2 b01 = bp[0], b23 = bp[1];
            ull b[4] = {b01.x, b01.y, b23.x, b23.y};
#pragma unroll
            for (int i = 0; i < 8; i++)
#pragma unroll
                for (int j = 0; j < 4; j++) acc[i][j] = f2(a[i], b[j], acc[i][j]);
        }
        __syncthreads();
    }

#pragma unroll
    for (int i = 0; i < 8; i++) {
        int m = bm + mOff + i;
        float* o = g_xg + (long)m * G5 + bn + nOff;
#pragma unroll
        for (int j = 0; j < 4; j++) {
            float2 v = up(acc[i][j]);
            o[2 * j]     = v.x + bias[bn + nOff + 2 * j];
            o[2 * j + 1] = v.y + bias[bn + nOff + 2 * j + 1];
        }
    }
}

// ---------------------------------------------------------------------------
// Per-m-group barrier (16 blocks): release-arrive + acquire-spin.
// ---------------------------------------------------------------------------
__device__ __forceinline__ void grp_bar(unsigned* ctr, unsigned target) {
    __syncthreads();
    if (threadIdx.x == 0) {
        asm volatile("red.release.gpu.global.add.u32 [%0], %1;"
                     :: "l"(ctr), "r"(1u) : "memory");
        unsigned v;
        do {
            asm volatile("ld.acquire.gpu.global.u32 %0, [%1];"
                         : "=r"(v) : "l"(ctr) : "memory");
        } while (v < target);
    }
    __syncthreads();
}

// ---------------------------------------------------------------------------
// Weight-tile prefetch (barrier-independent; issue BEFORE arriving).
// ---------------------------------------------------------------------------
template <int G>
__device__ __forceinline__ void prefB(const float* __restrict__ W, int ldw,
                                      int u0, int* bso, long* bgo, float4* pb) {
    const int tid = threadIdx.x;
#pragma unroll
    for (int r = 0; r < 2 * G; r++) {
        int fi  = tid + r * NTHR;
        int kk  = fi / (8 * G);
        int rem = fi - kk * 8 * G;
        int g   = rem >> 3;
        int u4  = (rem & 7) * 4;
        bso[r] = (kk * G + g) * BSL + u4;
        bgo[r] = (long)kk * ldw + g * U_ + u0 + u4;
        pb[r]  = __ldg((const float4*)(W + bgo[r]));
    }
}

// ---------------------------------------------------------------------------
// K-split tile GEMM (weights pre-fetched): 8 warps = 2 sets x 4 warps.
// Block tile 32m x (G x 32u); set S handles kk = S*32+[0,32) of each chunk.
// acc[g*4 + i*2 + p]: i = m sub-row, p = u-pair.
// ---------------------------------------------------------------------------
template <int G>
__device__ __forceinline__ void mm_tile(float* As, float* Bs,
                                        const float* __restrict__ Asrc,
                                        const float* __restrict__ W, int ldw,
                                        int m0, const int* bso, const long* bgo,
                                        float4* pb, ull* acc) {
    const int tid  = threadIdx.x;
    const int lane = tid & 31;
    const int wrp  = tid >> 5;
    const int S    = wrp >> 2;
    const int w4   = wrp & 3;
    const int mG = lane & 3, uG = lane >> 2;
    const int aOff = w4 * 8 + mG * 2;
    const int mA   = tid >> 3;
    const int kA   = (tid & 7) * 8;

#pragma unroll
    for (int i = 0; i < 4 * G; i++) acc[i] = 0ull;

    const float* Ap = Asrc + (m0 + mA) * U_ + kA;
    float4 pa0 = __ldcg((const float4*)(Ap));
    float4 pa1 = __ldcg((const float4*)(Ap + 4));

    for (int k0 = 0; k0 < U_; k0 += KT2) {
        __syncthreads();
        *(float4*)(As + mA * ASTR + kA)     = pa0;
        *(float4*)(As + mA * ASTR + kA + 4) = pa1;
#pragma unroll
        for (int r = 0; r < 2 * G; r++)
            *(float4*)(Bs + bso[r]) = pb[r];
        __syncthreads();
        if (k0 + KT2 < U_) {
            pa0 = __ldcg((const float4*)(Ap + k0 + KT2));
            pa1 = __ldcg((const float4*)(Ap + k0 + KT2 + 4));
#pragma unroll
            for (int r = 0; r < 2 * G; r++)
                pb[r] = __ldg((const float4*)(W + (long)(k0 + KT2) * ldw + bgo[r]));
        }
        const float* A0p = As + (aOff + 0) * ASTR + S * 32;
        const float* A1p = As + (aOff + 1) * ASTR + S * 32;
        const float* Bbase = Bs + (S * 32) * G * BSL + uG * 4;
#pragma unroll 8
        for (int kk2 = 0; kk2 < 32; kk2++) {
            ull A0 = pk(A0p[kk2]);
            ull A1 = pk(A1p[kk2]);
            const float* Bk = Bbase + kk2 * G * BSL;
#pragma unroll
            for (int g = 0; g < G; g++) {
                ulonglong2 bb = *(const ulonglong2*)(Bk + g * BSL);
                acc[g * 4 + 0] = f2(A0, bb.x, acc[g * 4 + 0]);
                acc[g * 4 + 1] = f2(A0, bb.y, acc[g * 4 + 1]);
                acc[g * 4 + 2] = f2(A1, bb.x, acc[g * 4 + 2]);
                acc[g * 4 + 3] = f2(A1, bb.y, acc[g * 4 + 3]);
            }
        }
    }
}

// ---------------------------------------------------------------------------
// Symmetric cross-set reduction: each thread keeps m sub-row i == S and
// exchanges the other. After this, ALL 256 threads hold valid results for
// one m-row (entries acc[g*4 + S*2 + p]); epilogue runs block-wide.
// Red layout: [j*256 + tid], j = g*2+p  (conflict-free, thread-contiguous).
// ---------------------------------------------------------------------------
template <int G>
__device__ __forceinline__ void k_reduce_sym(ull* Red, ull* acc, int S) {
    const int tid = threadIdx.x;
    const int other = 1 - S;
    __syncthreads();                    // compute done with Bs
#pragma unroll
    for (int g = 0; g < G; g++)
#pragma unroll
        for (int p = 0; p < 2; p++)
            Red[(g * 2 + p) * 256 + tid] = acc[g * 4 + other * 2 + p];
    __syncthreads();
    const int partner = tid ^ 128;
#pragma unroll
    for (int g = 0; g < G; g++)
#pragma unroll
        for (int p = 0; p < 2; p++)
            acc[g * 4 + S * 2 + p] =
                a2(acc[g * 4 + S * 2 + p], Red[(g * 2 + p) * 256 + partner]);
}

__device__ __forceinline__ float4 gate4(ull lo, ull hi) {
    float2 a = up(lo), b = up(hi);
    return make_float4(a.x, a.y, b.x, b.y);
}

// ---------------------------------------------------------------------------
// Persistent scan kernel: 128 blocks x 256 threads, per-m-group barriers.
// ---------------------------------------------------------------------------
__global__ void __launch_bounds__(NTHR)
scan_kernel(const float* __restrict__ Wr, const float* __restrict__ Wt,
            const float* __restrict__ bias, const float* __restrict__ tbias,
            float* __restrict__ out) {
    __shared__ __align__(16) char pool[32 * ASTR * 4 + KT2 * 4 * BSL * 4];
    float* As = (float*)pool;
    float* Bs = (float*)(pool + 32 * ASTR * 4);
    ull*  Red = (ull*)Bs;               // 16KB overlay (G<=4: 8*256*8B)

    const int u0   = (blockIdx.x & 15) * 32;
    const int grp  = blockIdx.x >> 4;
    const int m0   = grp * 32;
    unsigned* ctr  = &g_bar_grp[grp * 32];
    const int tid  = threadIdx.x;
    const int lane = tid & 31;
    const int wrp  = tid >> 5;
    const int S    = wrp >> 2;
    const int mG = lane & 3;
    const int b    = m0 + (wrp & 3) * 8 + mG * 2 + S;  // this thread's row
    const int uB   = u0 + (lane >> 2) * 4;             // first of 4 u's

    const float* xrow = g_xg + (long)b * T_ * G5;
    float* hrow  = g_h   + (long)b * U_ + uB;
    float* h1arw = g_h1a + (long)b * U_ + uB;
    float* h1brw = g_h1b + (long)b * U_ + uB;

    // biases (loop-invariant)
    const float4 bz = __ldg((const float4*)(bias + G5 + uB));
    const float4 br = __ldg((const float4*)(bias + G5 + U_ + uB));
    const float4 bh = __ldg((const float4*)(bias + G5 + 2 * U_ + uB));
    const float4 bl = __ldg((const float4*)(bias + G5 + 3 * U_ + uB));
    const float4 t0z = __ldg((const float4*)(tbias + uB));
    const float4 t0r = __ldg((const float4*)(tbias + U_ + uB));
    const float4 t0h = __ldg((const float4*)(tbias + 2 * U_ + uB));
    const float4 t1z = __ldg((const float4*)(tbias + G3 + uB));
    const float4 t1r = __ldg((const float4*)(tbias + G3 + U_ + uB));
    const float4 t1h = __ldg((const float4*)(tbias + G3 + 2 * U_ + uB));

    unsigned barno = 0;
    ull acc[16];
    int  bso[8]; long bgo[8]; float4 pb[8];
    float4 h1v, hlv;

    const float* Wt1 = Wt + (long)U_ * G3;

    prefB<4>(Wr, G4, u0, bso, bgo, pb);

    for (int t = 0; t < T_; t++) {
        const float* xp = xrow + (long)t * G5;

        // ---- phase REC: hg = h @ Wr (4 gates) ----
        mm_tile<4>(As, Bs, g_h, Wr, G4, m0, bso, bgo, pb, acc);
        k_reduce_sym<4>(Red, acc, S);
        {
            float4 az = gate4(acc[0  + S * 2], acc[1  + S * 2]);
            float4 ar = gate4(acc[4  + S * 2], acc[5  + S * 2]);
            float4 ah = gate4(acc[8  + S * 2], acc[9  + S * 2]);
            float4 al = gate4(acc[12 + S * 2], acc[13 + S * 2]);
            float4 xz = __ldg((const float4*)(xp + uB));
            float4 xr = __ldg((const float4*)(xp + U_ + uB));
            float4 xh = __ldg((const float4*)(xp + 2 * U_ + uB));
            float4 hold = __ldcg((const float4*)hrow);
            float z, r;
            z = hsig(xz.x + az.x + bz.x); r = hsig(xr.x + ar.x + br.x);
            h1v.x = z * hold.x + (1.f - z) * tanhf(xh.x + r * (ah.x + bh.x));
            z = hsig(xz.y + az.y + bz.y); r = hsig(xr.y + ar.y + br.y);
            h1v.y = z * hold.y + (1.f - z) * tanhf(xh.y + r * (ah.y + bh.y));
            z = hsig(xz.z + az.z + bz.z); r = hsig(xr.z + ar.z + br.z);
            h1v.z = z * hold.z + (1.f - z) * tanhf(xh.z + r * (ah.z + bh.z));
            z = hsig(xz.w + az.w + bz.w); r = hsig(xr.w + ar.w + br.w);
            h1v.w = z * hold.w + (1.f - z) * tanhf(xh.w + r * (ah.w + bh.w));
            hlv = make_float4(al.x + bl.x, al.y + bl.y, al.z + bl.z, al.w + bl.w);
            __stcg((float4*)h1arw, h1v);
        }
        prefB<3>(Wt, G3, u0, bso, bgo, pb);
        grp_bar(ctr, ++barno * 16);

        // ---- phase T0 ----
        mm_tile<3>(As, Bs, g_h1a, Wt, G3, m0, bso, bgo, pb, acc);
        k_reduce_sym<3>(Red, acc, S);
        {
            float4 az = gate4(acc[0 + S * 2], acc[1 + S * 2]);
            float4 ar = gate4(acc[4 + S * 2], acc[5 + S * 2]);
            float4 ah = gate4(acc[8 + S * 2], acc[9 + S * 2]);
            float zt, rt;
            zt = hsig(az.x + t0z.x); rt = hsig(ar.x + t0r.x);
            h1v.x = zt * h1v.x + (1.f - zt) * tanhf(rt * (ah.x + t0h.x));
            zt = hsig(az.y + t0z.y); rt = hsig(ar.y + t0r.y);
            h1v.y = zt * h1v.y + (1.f - zt) * tanhf(rt * (ah.y + t0h.y));
            zt = hsig(az.z + t0z.z); rt = hsig(ar.z + t0r.z);
            h1v.z = zt * h1v.z + (1.f - zt) * tanhf(rt * (ah.z + t0h.z));
            zt = hsig(az.w + t0z.w); rt = hsig(ar.w + t0r.w);
            h1v.w = zt * h1v.w + (1.f - zt) * tanhf(rt * (ah.w + t0h.w));
            __stcg((float4*)h1brw, h1v);
        }
        prefB<3>(Wt1, G3, u0, bso, bgo, pb);
        grp_bar(ctr, ++barno * 16);

        // ---- phase T1 + final combine ----
        mm_tile<3>(As, Bs, g_h1b, Wt1, G3, m0, bso, bgo, pb, acc);
        k_reduce_sym<3>(Red, acc, S);
        {
            float4 az = gate4(acc[0 + S * 2], acc[1 + S * 2]);
            float4 ar = gate4(acc[4 + S * 2], acc[5 + S * 2]);
            float4 ah = gate4(acc[8 + S * 2], acc[9 + S * 2]);
            float4 xl  = __ldg((const float4*)(xp + 3 * U_ + uB));
            float4 xl2 = __ldg((const float4*)(xp + 4 * U_ + uB));
            float zt, rt, l;
            float4 ho;
            zt = hsig(az.x + t1z.x); rt = hsig(ar.x + t1r.x);
            l  = hsig(xl.x + hlv.x);
            ho.x = l * (zt * h1v.x + (1.f - zt) * tanhf(rt * (ah.x + t1h.x)))
                 + (1.f - l) * tanhf(xl2.x);
            zt = hsig(az.y + t1z.y); rt = hsig(ar.y + t1r.y);
            l  = hsig(xl.y + hlv.y);
            ho.y = l * (zt * h1v.y + (1.f - zt) * tanhf(rt * (ah.y + t1h.y)))
                 + (1.f - l) * tanhf(xl2.y);
            zt = hsig(az.z + t1z.z); rt = hsig(ar.z + t1r.z);
            l  = hsig(xl.z + hlv.z);
            ho.z = l * (zt * h1v.z + (1.f - zt) * tanhf(rt * (ah.z + t1h.z)))
                 + (1.f - l) * tanhf(xl2.z);
            zt = hsig(az.w + t1z.w); rt = hsig(ar.w + t1r.w);
            l  = hsig(xl.w + hlv.w);
            ho.w = l * (zt * h1v.w + (1.f - zt) * tanhf(rt * (ah.w + t1h.w)))
                 + (1.f - l) * tanhf(xl2.w);
            __stcg((float4*)hrow, ho);
            *(float4*)(out + ((long)b * T_ + t) * U_ + uB) = ho;
        }
        prefB<4>(Wr, G4, u0, bso, bgo, pb);
        grp_bar(ctr, ++barno * 16);
    }
}

// ---------------------------------------------------------------------------
extern "C" void kernel_launch(void* const* d_in, const int* in_sizes, int n_in,
                              void* d_out, int out_size) {
    (void)in_sizes; (void)n_in; (void)out_size;
    const float* x      = (const float*)d_in[0];
    const float* h0     = (const float*)d_in[1];
    const float* kernel = (const float*)d_in[2];
    const float* Wr     = (const float*)d_in[3];
    const float* Wt     = (const float*)d_in[4];
    const float* bias   = (const float*)d_in[5];
    const float* tbias  = (const float*)d_in[6];
    float* out = (float*)d_out;

    init_h_kernel<<<(B_ * U_ + 255) / 256, 256>>>(h0);
    xg_gemm_kernel<<<dim3(G5 / 128, (B_ * T_) / 128), 256>>>(x, kernel, bias);
    scan_kernel<<<NBLK, NTHR>>>(Wr, Wt, bias, tbias, out);
}

// round 14
// speedup vs baseline: 1.1442x; 1.1442x over previous
#include <cuda_runtime.h>
#include <math.h>

// Problem constants
#define B_ 256
#define T_ 128
#define D_ 256
#define U_ 512
#define G5 2560   // 5*U
#define G4 2048   // 4*U
#define G3 1536   // 3*U

#define NBLK 128
#define NTHR 256          // 8 warps, 2 K-split sets
#define KT2 64            // staged K chunk
#define ASTR 68           // A smem row stride ([m][k], floats)
#define BSL 32            // B smem stride per (kk,gate): exactly 128B
#define ABUF (32 * ASTR)          // 2176 floats per A buffer
#define BBUF (KT2 * 4 * BSL)      // 8192 floats per B buffer
#define SMEM_BYTES ((2 * ABUF + 2 * BBUF) * 4)   // 82944

// Scratch (device globals: allocation-free per harness rules)
__device__ float g_xg[(long)B_ * T_ * G5];
__device__ float g_h [B_ * U_];
__device__ float g_h1a[B_ * U_];
__device__ float g_h1b[B_ * U_];
__device__ unsigned g_bar_ctr;

__device__ __forceinline__ float hsig(float x) {
    return fminf(fmaxf(0.2f * x + 0.5f, 0.0f), 1.0f);
}

typedef unsigned long long ull;
__device__ __forceinline__ ull pk(float x) {
    ull r; asm("mov.b64 %0, {%1, %1};" : "=l"(r) : "f"(x)); return r;
}
__device__ __forceinline__ ull f2(ull a, ull b, ull c) {
    ull d; asm("fma.rn.f32x2 %0, %1, %2, %3;" : "=l"(d) : "l"(a), "l"(b), "l"(c));
    return d;
}
__device__ __forceinline__ ull a2(ull a, ull b) {
    ull d; asm("add.rn.f32x2 %0, %1, %2;" : "=l"(d) : "l"(a), "l"(b));
    return d;
}
__device__ __forceinline__ float2 up(ull v) {
    float2 r; asm("mov.b64 {%0, %1}, %2;" : "=f"(r.x), "=f"(r.y) : "l"(v));
    return r;
}
__device__ __forceinline__ void pf(const void* p) {
    asm volatile("prefetch.global.L2 [%0];" :: "l"(p));
}

// ---------------------------------------------------------------------------
__global__ void init_h_kernel(const float* __restrict__ h0) {
    int i = blockIdx.x * blockDim.x + threadIdx.x;
    if (i < B_ * U_) g_h[i] = h0[i];
    if (i == 0) g_bar_ctr = 0;
}

// ---------------------------------------------------------------------------
// xg = x @ kernel + bias[0].  (known-good R8 version)
// ---------------------------------------------------------------------------
#define XASL 132
__global__ void __launch_bounds__(256)
xg_gemm_kernel(const float* __restrict__ X,
               const float* __restrict__ W,
               const float* __restrict__ bias) {
    __shared__ float As[8 * XASL];
    __shared__ float Bs[8 * 128];
    const int bm = blockIdx.y * 128;
    const int bn = blockIdx.x * 128;
    const int tid  = threadIdx.x;
    const int lane = tid & 31;
    const int wrp  = tid >> 5;
    const int mG = lane & 3, nG = lane >> 2;
    const int mW = wrp & 3,  nW = wrp >> 2;
    const int mOff = mW * 32 + mG * 8;
    const int nOff = nW * 64 + nG * 8;
    const int arow = tid >> 1, acol = (tid & 1) * 4;
    const int brow = tid >> 5, bcol = (tid & 31) * 4;

    ull acc[8][4];
#pragma unroll
    for (int i = 0; i < 8; i++)
#pragma unroll
        for (int j = 0; j < 4; j++) acc[i][j] = 0ull;

    const float* Xp = X + (bm + arow) * D_ + acol;
    const float* Wp = W + brow * G5 + bn + bcol;

    for (int k0 = 0; k0 < D_; k0 += 8) {
        float4 av = *(const float4*)(Xp + k0);
        As[(acol + 0) * XASL + arow] = av.x;
        As[(acol + 1) * XASL + arow] = av.y;
        As[(acol + 2) * XASL + arow] = av.z;
        As[(acol + 3) * XASL + arow] = av.w;
        *(float4*)&Bs[brow * 128 + bcol] = *(const float4*)(Wp + (long)k0 * G5);
        __syncthreads();
#pragma unroll
        for (int k = 0; k < 8; k++) {
            float4 a0 = *(const float4*)(As + k * XASL + mOff);
            float4 a1 = *(const float4*)(As + k * XASL + mOff + 4);
            ull a[8] = {pk(a0.x), pk(a0.y), pk(a0.z), pk(a0.w),
                        pk(a1.x), pk(a1.y), pk(a1.z), pk(a1.w)};
            const ulonglong2* bp = (const ulonglong2*)(Bs + k * 128 + nOff);
            ulonglong2 b01 = bp[0], b23 = bp[1];
            ull b[4] = {b01.x, b01.y, b23.x, b23.y};
#pragma unroll
            for (int i = 0; i < 8; i++)
#pragma unroll
                for (int j = 0; j < 4; j++) acc[i][j] = f2(a[i], b[j], acc[i][j]);
        }
        __syncthreads();
    }

#pragma unroll
    for (int i = 0; i < 8; i++) {
        int m = bm + mOff + i;
        float* o = g_xg + (long)m * G5 + bn + nOff;
#pragma unroll
        for (int j = 0; j < 4; j++) {
            float2 v = up(acc[i][j]);
            o[2 * j]     = v.x + bias[bn + nOff + 2 * j];
            o[2 * j + 1] = v.y + bias[bn + nOff + 2 * j + 1];
        }
    }
}

// ---------------------------------------------------------------------------
// Grid-wide barrier: release-arrive + acquire-spin (known-good R9).
// ---------------------------------------------------------------------------
__device__ __forceinline__ void grid_bar(unsigned target) {
    __syncthreads();
    if (threadIdx.x == 0) {
        asm volatile("red.release.gpu.global.add.u32 [%0], %1;"
                     :: "l"(&g_bar_ctr), "r"(1u) : "memory");
        unsigned v;
        do {
            asm volatile("ld.acquire.gpu.global.u32 %0, [%1];"
                         : "=r"(v) : "l"(&g_bar_ctr) : "memory");
        } while (v < target);
    }
    __syncthreads();
}

// ---------------------------------------------------------------------------
// Pre-stage W chunk 0 of the NEXT phase into Bs buf0 (local smem only;
// no ordering needed vs the barrier, nothing held across the spin).
// Call AFTER k_reduce (Red overlays buf1; this writes buf0).
// ---------------------------------------------------------------------------
template <int G>
__device__ __forceinline__ void preW(const float* __restrict__ W, int ldw,
                                     int u0, float* Bs0) {
    const int tid = threadIdx.x;
    float4 v[2 * G]; int so[2 * G];
#pragma unroll
    for (int r = 0; r < 2 * G; r++) {
        int fi  = tid + r * NTHR;
        int kk  = fi / (8 * G);
        int rem = fi - kk * 8 * G;
        int g   = rem >> 3;
        int u4  = (rem & 7) * 4;
        so[r] = (kk * G + g) * BSL + u4;
        v[r]  = __ldg((const float4*)(W + (long)kk * ldw + g * U_ + u0 + u4));
    }
#pragma unroll
    for (int r = 0; r < 2 * G; r++) *(float4*)(Bs0 + so[r]) = v[r];
}

// ---------------------------------------------------------------------------
// Double-buffered K-split tile GEMM. Assumes W chunk0 pre-staged in Bs buf0.
// 8 warps = 2 K-sets x 4 warps; block tile 32m x (G x 32u).
// One __syncthreads per chunk; STS of chunk c+1 overlaps compute of chunk c.
// ---------------------------------------------------------------------------
template <int G>
__device__ __forceinline__ void mm_tile_db(float* As, float* Bs,
                                           const float* __restrict__ Asrc,
                                           const float* __restrict__ W, int ldw,
                                           int m0, int u0, ull* acc) {
    const int tid  = threadIdx.x;
    const int lane = tid & 31;
    const int wrp  = tid >> 5;
    const int S    = wrp >> 2;
    const int w4   = wrp & 3;
    const int mG = lane & 3, uG = lane >> 2;
    const int aOff = w4 * 8 + mG * 2;
    const int mA   = tid >> 3;
    const int kA   = (tid & 7) * 8;

#pragma unroll
    for (int i = 0; i < 4 * G; i++) acc[i] = 0ull;

    int bso[2 * G];
    int bgo[2 * G];                  // fits int: < U_*ldw
#pragma unroll
    for (int r = 0; r < 2 * G; r++) {
        int fi  = tid + r * NTHR;
        int kk  = fi / (8 * G);
        int rem = fi - kk * 8 * G;
        int g   = rem >> 3;
        int u4  = (rem & 7) * 4;
        bso[r] = (kk * G + g) * BSL + u4;
        bgo[r] = kk * ldw + g * U_ + u0 + u4;
    }
    const float* Ap = Asrc + (m0 + mA) * U_ + kA;

    // chunk0 A + chunk1 A/W loads
    float4 pa0 = __ldcg((const float4*)(Ap));
    float4 pa1 = __ldcg((const float4*)(Ap + 4));
    float4 pb[2 * G];
#pragma unroll
    for (int r = 0; r < 2 * G; r++)
        pb[r] = __ldg((const float4*)(W + (long)KT2 * ldw + bgo[r]));
    float4 qa0 = __ldcg((const float4*)(Ap + KT2));
    float4 qa1 = __ldcg((const float4*)(Ap + KT2 + 4));
    // stage A0 into buf0 (W0 already there via preW)
    *(float4*)(As + mA * ASTR + kA)     = pa0;
    *(float4*)(As + mA * ASTR + kA + 4) = pa1;
    __syncthreads();

#pragma unroll
    for (int c = 0; c < 8; c++) {
        if (c < 7) {
            // stage chunk c+1 (regs loaded one iteration ago)
            float* Asn = As + ((c + 1) & 1) * ABUF;
            float* Bsn = Bs + ((c + 1) & 1) * BBUF;
            *(float4*)(Asn + mA * ASTR + kA)     = qa0;
            *(float4*)(Asn + mA * ASTR + kA + 4) = qa1;
#pragma unroll
            for (int r = 0; r < 2 * G; r++)
                *(float4*)(Bsn + bso[r]) = pb[r];
            if (c < 6) {
                qa0 = __ldcg((const float4*)(Ap + (c + 2) * KT2));
                qa1 = __ldcg((const float4*)(Ap + (c + 2) * KT2 + 4));
#pragma unroll
                for (int r = 0; r < 2 * G; r++)
                    pb[r] = __ldg((const float4*)(W + (long)(c + 2) * KT2 * ldw
                                                  + bgo[r]));
            }
        }
        const float* Asb = As + (c & 1) * ABUF;
        const float* Bsb = Bs + (c & 1) * BBUF;
        const float* A0p = Asb + (aOff + 0) * ASTR + S * 32;
        const float* A1p = Asb + (aOff + 1) * ASTR + S * 32;
        const float* Bbase = Bsb + (S * 32) * G * BSL + uG * 4;
#pragma unroll 8
        for (int kk2 = 0; kk2 < 32; kk2++) {
            ull A0 = pk(A0p[kk2]);
            ull A1 = pk(A1p[kk2]);
            const float* Bk = Bbase + kk2 * G * BSL;
#pragma unroll
            for (int g = 0; g < G; g++) {
                ulonglong2 bb = *(const ulonglong2*)(Bk + g * BSL);
                acc[g * 4 + 0] = f2(A0, bb.x, acc[g * 4 + 0]);
                acc[g * 4 + 1] = f2(A0, bb.y, acc[g * 4 + 1]);
                acc[g * 4 + 2] = f2(A1, bb.x, acc[g * 4 + 2]);
                acc[g * 4 + 3] = f2(A1, bb.y, acc[g * 4 + 3]);
            }
        }
        if (c < 7) __syncthreads();
    }
}

// ---------------------------------------------------------------------------
// Cross-set reduction (R9): set 1 dumps partials into Red (= Bs buf1),
// set 0 accumulates. Valid full acc in tid < 128 afterwards.
// ---------------------------------------------------------------------------
template <int G>
__device__ __forceinline__ void k_reduce(ull* Red, ull* acc) {
    const int tid = threadIdx.x;
    __syncthreads();
    if (tid >= 128) {
#pragma unroll
        for (int j = 0; j < 4 * G; j++) Red[(tid - 128) * 17 + j] = acc[j];
    }
    __syncthreads();
    if (tid < 128) {
#pragma unroll
        for (int j = 0; j < 4 * G; j++) acc[j] = a2(acc[j], Red[tid * 17 + j]);
    }
}

// ---------------------------------------------------------------------------
// Persistent scan kernel: 128 blocks x 256 threads, dynamic smem.
// ---------------------------------------------------------------------------
__global__ void __launch_bounds__(NTHR)
scan_kernel(const float* __restrict__ Wr, const float* __restrict__ Wt,
            const float* __restrict__ bias, const float* __restrict__ tbias,
            float* __restrict__ out) {
    extern __shared__ __align__(16) float smem[];
    float* As = smem;                   // 2 x ABUF
    float* Bs = smem + 2 * ABUF;        // 2 x BBUF
    ull*  Red = (ull*)(Bs + BBUF);      // overlays buf1

    const int u0   = (blockIdx.x & 15) * 32;
    const int m0   = (blockIdx.x >> 4) * 32;
    const int tid  = threadIdx.x;
    const int lane = tid & 31;
    const int wrp  = tid >> 5;
    const int mG = lane & 3;
    const int mBase = m0 + (wrp & 3) * 8 + mG * 2;
    const int uBase = u0 + (lane >> 2) * 4;

    const float* Wt1 = Wt + (long)U_ * G3;

    unsigned barno = 0;
    ull acc[16];
    float h1r[2][2][2];   // [i][p][h2]  (valid in tid<128)
    float hlr[2][2][2];

    preW<4>(Wr, G4, u0, Bs);            // W chunk0 for the first REC

    for (int t = 0; t < T_; t++) {
        // L2-prefetch this step's xg epilogue lines (cold DRAM otherwise)
        if (tid < 128) {
#pragma unroll
            for (int i = 0; i < 2; i++) {
                const float* xq = g_xg + ((long)(mBase + i) * T_ + t) * G5 + uBase;
                pf(xq); pf(xq + U_); pf(xq + 2 * U_); pf(xq + 3 * U_); pf(xq + 4 * U_);
            }
        }

        // ---- phase REC: hg = h @ Wr (4 gates: z, r, hr, l) ----
        mm_tile_db<4>(As, Bs, g_h, Wr, G4, m0, u0, acc);
        k_reduce<4>(Red, acc);
        if (tid < 128) {
#pragma unroll
            for (int i = 0; i < 2; i++) {
                const int b = mBase + i;
                const float* xp = g_xg + ((long)b * T_ + t) * G5;
#pragma unroll
                for (int p = 0; p < 2; p++) {
                    float2 vz = up(acc[0  + i * 2 + p]);
                    float2 vr = up(acc[4  + i * 2 + p]);
                    float2 vh = up(acc[8  + i * 2 + p]);
                    float2 vl = up(acc[12 + i * 2 + p]);
#pragma unroll
                    for (int h2 = 0; h2 < 2; h2++) {
                        const int u = uBase + p * 2 + h2;
                        float az = h2 ? vz.y : vz.x;
                        float ar = h2 ? vr.y : vr.x;
                        float ah = h2 ? vh.y : vh.x;
                        float al = h2 ? vl.y : vl.x;
                        float z  = hsig(__ldg(xp + u) + az + __ldg(bias + G5 + u));
                        float r  = hsig(__ldg(xp + U_ + u) + ar +
                                        __ldg(bias + G5 + U_ + u));
                        float hh = tanhf(__ldg(xp + 2 * U_ + u) +
                                         r * (ah + __ldg(bias + G5 + 2 * U_ + u)));
                        float hold = __ldcg(g_h + (long)b * U_ + u);
                        float h1 = z * hold + (1.0f - z) * hh;
                        __stcg(g_h1a + (long)b * U_ + u, h1);
                        h1r[i][p][h2] = h1;
                        hlr[i][p][h2] = al + __ldg(bias + G5 + 3 * U_ + u);
                    }
                }
            }
        }
        preW<3>(Wt, G3, u0, Bs);
        grid_bar(++barno * NBLK);

        // ---- phase T0 ----
        mm_tile_db<3>(As, Bs, g_h1a, Wt, G3, m0, u0, acc);
        k_reduce<3>(Red, acc);
        if (tid < 128) {
#pragma unroll
            for (int i = 0; i < 2; i++) {
                const int b = mBase + i;
#pragma unroll
                for (int p = 0; p < 2; p++) {
                    float2 vz = up(acc[0 + i * 2 + p]);
                    float2 vr = up(acc[4 + i * 2 + p]);
                    float2 vh = up(acc[8 + i * 2 + p]);
#pragma unroll
                    for (int h2 = 0; h2 < 2; h2++) {
                        const int u = uBase + p * 2 + h2;
                        float az = h2 ? vz.y : vz.x;
                        float ar = h2 ? vr.y : vr.x;
                        float ah = h2 ? vh.y : vh.x;
                        float zt = hsig(az + __ldg(tbias + u));
                        float rt = hsig(ar + __ldg(tbias + U_ + u));
                        float ht = tanhf(rt * (ah + __ldg(tbias + 2 * U_ + u)));
                        float h1 = zt * h1r[i][p][h2] + (1.0f - zt) * ht;
                        __stcg(g_h1b + (long)b * U_ + u, h1);
                        h1r[i][p][h2] = h1;
                    }
                }
            }
        }
        preW<3>(Wt1, G3, u0, Bs);
        grid_bar(++barno * NBLK);

        // ---- phase T1 + final combine ----
        mm_tile_db<3>(As, Bs, g_h1b, Wt1, G3, m0, u0, acc);
        k_reduce<3>(Red, acc);
        if (tid < 128) {
#pragma unroll
            for (int i = 0; i < 2; i++) {
                const int b = mBase + i;
                const float* xp = g_xg + ((long)b * T_ + t) * G5;
#pragma unroll
                for (int p = 0; p < 2; p++) {
                    float2 vz = up(acc[0 + i * 2 + p]);
                    float2 vr = up(acc[4 + i * 2 + p]);
                    float2 vh = up(acc[8 + i * 2 + p]);
#pragma unroll
                    for (int h2 = 0; h2 < 2; h2++) {
                        const int u = uBase + p * 2 + h2;
                        float az = h2 ? vz.y : vz.x;
                        float ar = h2 ? vr.y : vr.x;
                        float ah = h2 ? vh.y : vh.x;
                        float zt = hsig(az + __ldg(tbias + G3 + u));
                        float rt = hsig(ar + __ldg(tbias + G3 + U_ + u));
                        float ht = tanhf(rt * (ah + __ldg(tbias + G3 + 2 * U_ + u)));
                        float h1 = zt * h1r[i][p][h2] + (1.0f - zt) * ht;
                        float l  = hsig(__ldg(xp + 3 * U_ + u) + hlr[i][p][h2]);
                        float ho = l * h1 +
                                   (1.0f - l) * tanhf(__ldg(xp + 4 * U_ + u));
                        __stcg(g_h + (long)b * U_ + u, ho);
                        out[((long)b * T_ + t) * U_ + u] = ho;
                    }
                }
            }
        }
        preW<4>(Wr, G4, u0, Bs);
        grid_bar(++barno * NBLK);
    }
}

// ---------------------------------------------------------------------------
extern "C" void kernel_launch(void* const* d_in, const int* in_sizes, int n_in,
                              void* d_out, int out_size) {
    (void)in_sizes; (void)n_in; (void)out_size;
    const float* x      = (const float*)d_in[0];
    const float* h0     = (const float*)d_in[1];
    const float* kernel = (const float*)d_in[2];
    const float* Wr     = (const float*)d_in[3];
    const float* Wt     = (const float*)d_in[4];
    const float* bias   = (const float*)d_in[5];
    const float* tbias  = (const float*)d_in[6];
    float* out = (float*)d_out;

    static int smem_set = 0;
    if (!smem_set) {
        cudaFuncSetAttribute(scan_kernel,
                             cudaFuncAttributeMaxDynamicSharedMemorySize,
                             SMEM_BYTES);
        smem_set = 1;
    }

    init_h_kernel<<<(B_ * U_ + 255) / 256, 256>>>(h0);
    xg_gemm_kernel<<<dim3(G5 / 128, (B_ * T_) / 128), 256>>>(x, kernel, bias);
    scan_kernel<<<NBLK, NTHR, SMEM_BYTES>>>(Wr, Wt, bias, tbias, out);
}